// round 16
// baseline (speedup 1.0000x reference)
#include <cuda_runtime.h>
#include <math.h>
#include <stdint.h>

#define Bsz 4
#define Ssz 2048
#define Dsz 1024
#define Hsz 4
#define HDsz 256
#define BS (Bsz*Ssz)          /* 8192 rows */
typedef long long ll;

/* ------------------------------------------------------------------ */
/* scratch (device globals — no allocation in kernel_launch)          */
/* ------------------------------------------------------------------ */
__device__ float g_ln  [(ll)BS*Dsz];
__device__ float g_lnE [(ll)BS*Dsz];
__device__ float g_big [(ll)BS*4*Dsz];
__device__ float g_mid [(ll)BS*Dsz];
__device__ float g_att [(ll)BS*Dsz];
__device__ float g_e1  [(ll)BS*Dsz];
__device__ float g_d1  [(ll)BS*Dsz];
__device__ float g_dmid[(ll)BS*Dsz];
__device__ float g_sc  [(ll)Bsz*Hsz*Ssz*Ssz];
__device__ float g_rsp [(ll)Bsz*Hsz*Ssz*16];
__device__ float g_rs  [(ll)Bsz*Hsz*Ssz];
__device__ float g_meanp[(ll)256*Dsz];
__device__ float g_mean_e[Bsz*Dsz];
__device__ float g_mean_d[Bsz*Dsz];
__device__ int   g_sel[4];

/* ------------------------------------------------------------------ */
__global__ void __launch_bounds__(256) mean1b_k(const float* __restrict__ x0,
                                                const float* __restrict__ x1,
                                                float* __restrict__ partial) {
    int blk = blockIdx.x;
    const float* x = (blk < 128) ? x0 : x1;
    int lb = blk & 127;
    int b = lb >> 5, ch = lb & 31;
    const float* p = x + (ll)b * Ssz * Dsz + (ll)ch * 64 * Dsz;
    int d4 = threadIdx.x;
    float4 acc = make_float4(0.f, 0.f, 0.f, 0.f);
    for (int r = 0; r < 64; r++) {
        float4 v = *(const float4*)(p + (ll)r * Dsz + d4 * 4);
        acc.x += v.x; acc.y += v.y; acc.z += v.z; acc.w += v.w;
    }
    *(float4*)(partial + (ll)blk * Dsz + d4 * 4) = acc;
}
__global__ void mean2b_k(const float* __restrict__ partial,
                         float* __restrict__ oe, float* __restrict__ od) {
    int idx = blockIdx.x * blockDim.x + threadIdx.x;
    if (idx >= 2 * Bsz * Dsz) return;
    int half = idx / (Bsz * Dsz);
    int li = idx - half * (Bsz * Dsz);
    int b = li / Dsz, d = li % Dsz;
    const float* p = partial + (ll)half * 128 * Dsz + (ll)b * 32 * Dsz + d;
    float s = 0.f;
    #pragma unroll
    for (int c = 0; c < 32; c++) s += p[(ll)c * Dsz];
    float* out = half ? od : oe;
    out[li] = s * (1.0f / Ssz);
}

__global__ void route2_k(const float* __restrict__ me, const float* __restrict__ md,
                         const float* __restrict__ esw, const float* __restrict__ esb,
                         const float* __restrict__ dsw, const float* __restrict__ dsb,
                         int* __restrict__ selOut) {
    int zz = blockIdx.x;
    const float* mean0 = zz ? md : me;
    const float* selw  = zz ? dsw : esw;
    const float* selb  = zz ? dsb : esb;
    int* out = selOut + zz * 2;
    __shared__ float sc[8];
    int w = threadIdx.x >> 5, lane = threadIdx.x & 31;
    float s = 0.f;
    for (int i = lane; i < Dsz; i += 32) s += mean0[i] * selw[w * Dsz + i];
    #pragma unroll
    for (int o = 16; o; o >>= 1) s += __shfl_down_sync(0xffffffff, s, o);
    if (lane == 0) sc[w] = s + selb[w];
    __syncthreads();
    if (threadIdx.x == 0) {
        int i0 = 0;
        for (int i = 1; i < 8; i++) if (sc[i] > sc[i0]) i0 = i;
        int i1 = -1;
        for (int i = 0; i < 8; i++)
            if (i != i0 && (i1 < 0 || sc[i] > sc[i1])) i1 = i;
        out[0] = i0; out[1] = i1;
    }
}

__global__ void __launch_bounds__(256) ln_k(const float* __restrict__ x,
                                            float* __restrict__ y,
                                            const float* __restrict__ sBase,
                                            const float* __restrict__ bBase,
                                            const int* __restrict__ sel, int step) {
    int row = blockIdx.x;
    const float* xr = x + (ll)row * Dsz;
    float*       yr = y + (ll)row * Dsz;
    int s = sel[step];
    const float* sc = sBase + (ll)s * Dsz;
    const float* bi = bBase + (ll)s * Dsz;
    int tid = threadIdx.x;
    float4 v = *(const float4*)(xr + tid * 4);
    float sum = v.x + v.y + v.z + v.w;
    float sq  = v.x*v.x + v.y*v.y + v.z*v.z + v.w*v.w;
    __shared__ float ssum[256], ssq[256];
    ssum[tid] = sum; ssq[tid] = sq;
    __syncthreads();
    for (int o = 128; o > 0; o >>= 1) {
        if (tid < o) { ssum[tid] += ssum[tid+o]; ssq[tid] += ssq[tid+o]; }
        __syncthreads();
    }
    float mean = ssum[0] * (1.0f / Dsz);
    float var  = ssq[0] * (1.0f / Dsz) - mean * mean;
    float inv  = rsqrtf(var + 1e-5f);
    float4 s4 = *(const float4*)(sc + tid * 4);
    float4 b4 = *(const float4*)(bi + tid * 4);
    float4 o4;
    o4.x = (v.x - mean) * inv * s4.x + b4.x;
    o4.y = (v.y - mean) * inv * s4.y + b4.y;
    o4.z = (v.z - mean) * inv * s4.z + b4.z;
    o4.w = (v.w - mean) * inv * s4.w + b4.w;
    *(float4*)(yr + tid * 4) = o4;
}

__global__ void rowsum2_k(const float* __restrict__ rsp, float* __restrict__ rs) {
    int row = blockIdx.x * 256 + threadIdx.x;
    const float* p = rsp + (ll)row * 16;
    float s = 0.f;
    #pragma unroll
    for (int i = 0; i < 16; i++) s += p[i];
    rs[row] = s;
}

/* ------------------------------------------------------------------ */
/* tf32 tensor-core GEMM, 128x128 tile, 3-stage cp.async, ldmatrix    */
/* EPI: 0 none 1 +bias 2 tanh 3 gelu 4 emb-res 5 outproj-res 6 ff2-res*/
/*      7 exp(alpha*g) + partial row sums   8 g/rowsum[z*2048+m]      */
/* ------------------------------------------------------------------ */
struct GemmP {
    const float* A; int lda; ll aO, aI;
    const float* W; int ldw; ll wO, wI;
    const float* bias;
    float* C; int ldc; ll cO, cI;
    int zdiv;
    int M, N, K;
    float alpha;
    const float* X; int ldx; ll xO, xI;
    const float* tf; const float* delayed;
    float* rsp;
    int Srows;
    const int* sel; int selStep; ll selW, selB;
};

__device__ __forceinline__ void mma_tf32(float4& c,
        uint32_t a0, uint32_t a1, uint32_t a2, uint32_t a3,
        uint32_t b0, uint32_t b1) {
    asm volatile(
        "mma.sync.aligned.m16n8k8.row.col.f32.tf32.tf32.f32 "
        "{%0,%1,%2,%3}, {%4,%5,%6,%7}, {%8,%9}, {%0,%1,%2,%3};"
        : "+f"(c.x), "+f"(c.y), "+f"(c.z), "+f"(c.w)
        : "r"(a0), "r"(a1), "r"(a2), "r"(a3), "r"(b0), "r"(b1));
}

__device__ __forceinline__ void cp_async16(void* dst, const void* src) {
    uint32_t s = (uint32_t)__cvta_generic_to_shared(dst);
    asm volatile("cp.async.cg.shared.global [%0], [%1], 16;" :: "r"(s), "l"(src));
}

__device__ __forceinline__ void ldm_x4(uint32_t* r, uint32_t addr) {
    asm volatile("ldmatrix.sync.aligned.m8n8.x4.shared.b16 {%0,%1,%2,%3}, [%4];"
        : "=r"(r[0]), "=r"(r[1]), "=r"(r[2]), "=r"(r[3]) : "r"(addr));
}

#define APAD 20     /* 16 + 4 pad, K-major row stride  */
#define BPAD 136    /* 128 + 8 pad, N-major row stride */
#define A_ELEMS (128*APAD)
#define BT_ELEMS (128*APAD)
#define BF_ELEMS (16*BPAD)

template<int EPI, bool BT>
__global__ void __launch_bounds__(256) gemm_k(GemmP p) {
    extern __shared__ float smem[];
    const int B_ELEMS = BT ? BT_ELEMS : BF_ELEMS;
    float* AsBase = smem;
    float* BsBase = smem + 3 * A_ELEMS;

    int z = blockIdx.z;
    int zo = z / p.zdiv, zi = z % p.zdiv;
    const float* A = p.A + zo * p.aO + zi * p.aI;
    const float* W = p.W + zo * p.wO + zi * p.wI;
    float*       C = p.C + zo * p.cO + zi * p.cI;
    const float* X = p.X ? (p.X + zo * p.xO + zi * p.xI) : nullptr;
    const float* bias = p.bias;
    if (p.sel) {
        int s = p.sel[p.selStep];
        W += (ll)s * p.selW;
        if (bias) bias += (ll)s * p.selB;
    }
    int m0 = blockIdx.y * 128, n0 = blockIdx.x * 128;
    int tid  = threadIdx.x;
    int lane = tid & 31;
    int warp = tid >> 5;
    int warpM = warp >> 2;
    int warpN = warp & 3;
    int lr = lane >> 2;
    int lc = lane & 3;

    int aRowSel = lane & 15;
    int aColSel = (lane >> 4) * 4;
    int bRowSel = (lane & 7) + ((lane >> 4) << 3);
    int bColSel = ((lane >> 3) & 1) * 4;

    uint32_t aBaseU = (uint32_t)__cvta_generic_to_shared(AsBase);
    uint32_t bBaseU = (uint32_t)__cvta_generic_to_shared(BsBase);

    float4 acc[4][4];
    #pragma unroll
    for (int i = 0; i < 4; i++)
        #pragma unroll
        for (int j = 0; j < 4; j++) acc[i][j] = make_float4(0.f, 0.f, 0.f, 0.f);

    auto issueStage = [&](int stage, int k0) {
        float* Ad = AsBase + stage * A_ELEMS;
        #pragma unroll
        for (int l = 0; l < 2; l++) {
            int idx = tid + l * 256;
            int r = idx >> 2, c4 = idx & 3;
            cp_async16(Ad + r * APAD + c4 * 4,
                       A + (ll)(m0 + r) * p.lda + k0 + c4 * 4);
        }
        float* Bd = BsBase + stage * B_ELEMS;
        if (BT) {
            #pragma unroll
            for (int l = 0; l < 2; l++) {
                int idx = tid + l * 256;
                int r = idx >> 2, c4 = idx & 3;
                cp_async16(Bd + r * APAD + c4 * 4,
                           W + (ll)(n0 + r) * p.ldw + k0 + c4 * 4);
            }
        } else {
            #pragma unroll
            for (int l = 0; l < 2; l++) {
                int idx = tid + l * 256;
                int kr = idx >> 5, c4 = idx & 31;
                cp_async16(Bd + kr * BPAD + c4 * 4,
                           W + (ll)(k0 + kr) * p.ldw + n0 + c4 * 4);
            }
        }
        asm volatile("cp.async.commit_group;" ::: "memory");
    };

    int nStages = p.K >> 4;
    issueStage(0, 0);
    if (nStages > 1) issueStage(1, 16);

    int s = 0;
    for (int i = 0; i < nStages; i++) {
        asm volatile("cp.async.wait_group 1;" ::: "memory");
        __syncthreads();
        if (i + 2 < nStages) {
            int ns = s + 2; if (ns >= 3) ns -= 3;
            issueStage(ns, (i + 2) << 4);
        }

        uint32_t aS = aBaseU + (s * A_ELEMS) * 4;
        uint32_t bS = bBaseU + (s * B_ELEMS) * 4;
        const float* Bsb = BsBase + s * B_ELEMS;

        #pragma unroll
        for (int kc = 0; kc < 2; kc++) {
            int kb = kc * 8;
            uint32_t af[4][4];
            #pragma unroll
            for (int mf = 0; mf < 4; mf++) {
                int rb = warpM * 64 + mf * 16;
                uint32_t addr = aS + (uint32_t)(((rb + aRowSel) * APAD + kb + aColSel) * 4);
                ldm_x4(af[mf], addr);
            }
            uint32_t bf[2][4];
            if (BT) {
                #pragma unroll
                for (int pr = 0; pr < 2; pr++) {
                    int nb = warpN * 32 + pr * 16;
                    uint32_t addr = bS + (uint32_t)(((nb + bRowSel) * APAD + kb + bColSel) * 4);
                    ldm_x4(bf[pr], addr);
                }
            } else {
                #pragma unroll
                for (int nf = 0; nf < 4; nf++) {
                    int nb = warpN * 32 + nf * 8;
                    bf[nf >> 1][(nf & 1) * 2    ] = __float_as_uint(Bsb[(kb + lc    ) * BPAD + nb + lr]);
                    bf[nf >> 1][(nf & 1) * 2 + 1] = __float_as_uint(Bsb[(kb + lc + 4) * BPAD + nb + lr]);
                }
            }
            #pragma unroll
            for (int mf = 0; mf < 4; mf++)
                #pragma unroll
                for (int nf = 0; nf < 4; nf++)
                    mma_tf32(acc[mf][nf],
                             af[mf][0], af[mf][1], af[mf][2], af[mf][3],
                             bf[nf >> 1][(nf & 1) * 2], bf[nf >> 1][(nf & 1) * 2 + 1]);
        }
        s++; if (s >= 3) s = 0;
    }

    /* epilogue */
    float rowPart[4][2];
    #pragma unroll
    for (int i = 0; i < 4; i++) { rowPart[i][0] = 0.f; rowPart[i][1] = 0.f; }

    #pragma unroll
    for (int mf = 0; mf < 4; mf++) {
        #pragma unroll
        for (int nf = 0; nf < 4; nf++) {
            float4 c = acc[mf][nf];
            float vals[4] = {c.x, c.y, c.z, c.w};
            #pragma unroll
            for (int e = 0; e < 4; e++) {
                int m = m0 + warpM * 64 + mf * 16 + lr + (e >= 2 ? 8 : 0);
                int n = n0 + warpN * 32 + nf * 8 + lc * 2 + (e & 1);
                int bb = m / p.Srows;
                float g = vals[e] * p.alpha;
                if (EPI >= 1 && EPI <= 6) g += bias[n];
                float r;
                if      (EPI == 0) r = g;
                else if (EPI == 1) r = g;
                else if (EPI == 2) r = tanhf(g);
                else if (EPI == 3) r = 0.5f * g * (1.0f + erff(g * 0.7071067811865475f));
                else if (EPI == 4) r = X[(ll)m * p.ldx + n]
                                       + g * (1.0f + p.tf[bb * Dsz + n] * 0.1f) * 0.3f;
                else if (EPI == 5) r = X[(ll)m * p.ldx + n]
                                       + (g + p.delayed[bb * Dsz + n] * 0.3f)
                                         * (1.0f + p.tf[bb * Dsz + n] * 0.05f) * 0.5f;
                else if (EPI == 6) r = X[(ll)m * p.ldx + n] + g * 0.5f;
                else if (EPI == 7) { r = __expf(g); rowPart[mf][e >> 1] += r; }
                else               r = g / p.tf[(ll)z * Ssz + m];   /* EPI 8 */
                C[(ll)m * p.ldc + n] = r;
            }
        }
    }

    if (EPI == 7) {
        __syncthreads();
        float* sPart = smem;
        #pragma unroll
        for (int mf = 0; mf < 4; mf++)
            #pragma unroll
            for (int e2 = 0; e2 < 2; e2++) {
                float v = rowPart[mf][e2];
                v += __shfl_xor_sync(0xffffffff, v, 1);
                v += __shfl_xor_sync(0xffffffff, v, 2);
                if (lc == 0) {
                    int rl = warpM * 64 + mf * 16 + lr + e2 * 8;
                    sPart[rl * 4 + warpN] = v;
                }
            }
        __syncthreads();
        if (tid < 128) {
            float t = sPart[tid * 4 + 0] + sPart[tid * 4 + 1]
                    + sPart[tid * 4 + 2] + sPart[tid * 4 + 3];
            p.rsp[((ll)z * Ssz + m0 + tid) * 16 + blockIdx.x] = t;
        }
    }
}

/* ------------------------------------------------------------------ */
#define SMEM_BT ((3*A_ELEMS + 3*BT_ELEMS) * (int)sizeof(float))
#define SMEM_BF ((3*A_ELEMS + 3*BF_ELEMS) * (int)sizeof(float))

template<int EPI, bool BT>
static void launch_gemm(const GemmP& p, dim3 grid, cudaStream_t st) {
    static bool done = false;
    if (!done) {
        cudaFuncSetAttribute(gemm_k<EPI, BT>,
                             cudaFuncAttributeMaxDynamicSharedMemorySize,
                             BT ? SMEM_BT : SMEM_BF);
        done = true;
    }
    gemm_k<EPI, BT><<<grid, 256, BT ? SMEM_BT : SMEM_BF, st>>>(p);
}

extern "C" void kernel_launch(void* const* d_in, const int* in_sizes, int n_in,
                              void* d_out, int out_size) {
    const float* emb_in  = (const float*)d_in[0];
    const float* dis_in  = (const float*)d_in[1];
    const float* tf      = (const float*)d_in[2];
    const float* esel_w  = (const float*)d_in[3];
    const float* esel_b  = (const float*)d_in[4];
    const float* e_ln_s  = (const float*)d_in[5];
    const float* e_ln_b  = (const float*)d_in[6];
    const float* e_w1    = (const float*)d_in[7];
    const float* e_b1    = (const float*)d_in[8];
    const float* e_w2    = (const float*)d_in[9];
    const float* e_b2    = (const float*)d_in[10];
    const float* dsel_w  = (const float*)d_in[11];
    const float* dsel_b  = (const float*)d_in[12];
    const float* d_ln1_s = (const float*)d_in[13];
    const float* d_ln1_b = (const float*)d_in[14];
    const float* d_qkv_w = (const float*)d_in[15];
    const float* d_qkv_b = (const float*)d_in[16];
    const float* d_out_w = (const float*)d_in[17];
    const float* d_out_b = (const float*)d_in[18];
    const float* d_ln2_s = (const float*)d_in[19];
    const float* d_ln2_b = (const float*)d_in[20];
    const float* d_ff1_w = (const float*)d_in[21];
    const float* d_ff1_b = (const float*)d_in[22];
    const float* d_ff2_w = (const float*)d_in[23];
    const float* d_ff2_b = (const float*)d_in[24];

    float *p_ln, *p_lnE, *p_big, *p_mid, *p_att, *p_e1, *p_d1, *p_dmid, *p_sc,
          *p_rsp, *p_rs, *p_mp, *p_me, *p_md;
    int   *p_sel;
    cudaGetSymbolAddress((void**)&p_ln,   g_ln);
    cudaGetSymbolAddress((void**)&p_lnE,  g_lnE);
    cudaGetSymbolAddress((void**)&p_big,  g_big);
    cudaGetSymbolAddress((void**)&p_mid,  g_mid);
    cudaGetSymbolAddress((void**)&p_att,  g_att);
    cudaGetSymbolAddress((void**)&p_e1,   g_e1);
    cudaGetSymbolAddress((void**)&p_d1,   g_d1);
    cudaGetSymbolAddress((void**)&p_dmid, g_dmid);
    cudaGetSymbolAddress((void**)&p_sc,   g_sc);
    cudaGetSymbolAddress((void**)&p_rsp,  g_rsp);
    cudaGetSymbolAddress((void**)&p_rs,   g_rs);
    cudaGetSymbolAddress((void**)&p_mp,   g_meanp);
    cudaGetSymbolAddress((void**)&p_me,   g_mean_e);
    cudaGetSymbolAddress((void**)&p_md,   g_mean_d);
    cudaGetSymbolAddress((void**)&p_sel,  g_sel);

    float* out_h  = (float*)d_out;
    float* out_dh = (float*)d_out + (ll)BS * Dsz;

    /* one-time stream/event setup */
    static cudaStream_t sE = nullptr, sV = nullptr;
    static cudaEvent_t evFork = nullptr, evJoin = nullptr;
    static cudaEvent_t evLND[2] = {nullptr, nullptr}, evV[2] = {nullptr, nullptr};
    if (!sE) {
        cudaStreamCreateWithFlags(&sE, cudaStreamNonBlocking);
        cudaStreamCreateWithFlags(&sV, cudaStreamNonBlocking);
        cudaEventCreateWithFlags(&evFork, cudaEventDisableTiming);
        cudaEventCreateWithFlags(&evJoin, cudaEventDisableTiming);
        for (int i = 0; i < 2; i++) {
            cudaEventCreateWithFlags(&evLND[i], cudaEventDisableTiming);
            cudaEventCreateWithFlags(&evV[i], cudaEventDisableTiming);
        }
    }
    cudaStream_t s0 = 0;

    mean1b_k<<<256, 256, 0, s0>>>(emb_in, dis_in, p_mp);
    mean2b_k<<<32, 256, 0, s0>>>(p_mp, p_me, p_md);
    route2_k<<<2, 256, 0, s0>>>(p_me, p_md, esel_w, esel_b, dsel_w, dsel_b, p_sel);

    cudaEventRecord(evFork, s0);
    cudaStreamWaitEvent(sE, evFork, 0);

    GemmP p;
    auto clear = [&](GemmP& q) {
        q.aO=q.aI=q.wO=q.wI=q.cO=q.cI=q.xO=q.xI=0; q.zdiv=1;
        q.alpha=1.0f; q.X=nullptr; q.ldx=0; q.tf=nullptr; q.delayed=nullptr;
        q.rsp=nullptr;
        q.Srows=Ssz; q.sel=nullptr; q.selStep=0; q.selW=0; q.selB=0; q.bias=nullptr;
    };

    /* ---------------- embodied path (stream sE) ---------------- */
    for (int it = 0; it < 2; it++) {
        const float* xin  = (it == 0) ? emb_in : p_e1;
        float*       xout = (it == 0) ? p_e1   : out_h;

        ln_k<<<BS, 256, 0, sE>>>(xin, p_lnE, e_ln_s, e_ln_b, p_sel, it);

        clear(p);
        p.A = p_lnE; p.lda = Dsz;
        p.W = e_w1;  p.ldw = Dsz;
        p.bias = e_b1;
        p.C = p_mid; p.ldc = Dsz;
        p.M = BS; p.N = Dsz; p.K = Dsz;
        p.sel = p_sel; p.selStep = it;
        p.selW = (ll)Dsz * Dsz; p.selB = Dsz;
        launch_gemm<2, true>(p, dim3(8, 64, 1), sE);

        clear(p);
        p.A = p_mid; p.lda = Dsz;
        p.W = e_w2;  p.ldw = Dsz;
        p.bias = e_b2;
        p.C = xout;  p.ldc = Dsz;
        p.M = BS; p.N = Dsz; p.K = Dsz;
        p.X = xin; p.ldx = Dsz; p.tf = tf;
        p.sel = p_sel; p.selStep = it;
        p.selW = (ll)Dsz * Dsz; p.selB = Dsz;
        launch_gemm<4, true>(p, dim3(8, 64, 1), sE);
    }

    /* ---------------- disembodied path (s0 + dedicated v-stream sV) -- */
    for (int it = 0; it < 2; it++) {
        const float* xin  = (it == 0) ? dis_in : p_d1;
        float*       xout = (it == 0) ? p_d1   : out_dh;
        int step = 2 + it;

        ln_k<<<BS, 256, 0, s0>>>(xin, p_ln, d_ln1_s, d_ln1_b, p_sel, step);
        cudaEventRecord(evLND[it], s0);

        /* v = ln @ Wv^T + bv on dedicated stream sV (ONLY v-GEMMs live here) */
        cudaStreamWaitEvent(sV, evLND[it], 0);
        clear(p);
        p.A = p_ln;                        p.lda = Dsz;
        p.W = d_qkv_w + (ll)2 * Dsz * Dsz; p.ldw = Dsz;
        p.bias = d_qkv_b + 2 * Dsz;
        p.C = p_big + 2 * Dsz;             p.ldc = 3 * Dsz;
        p.M = BS; p.N = Dsz; p.K = Dsz;
        p.sel = p_sel; p.selStep = step;
        p.selW = (ll)3 * Dsz * Dsz; p.selB = 3 * Dsz;
        launch_gemm<1, true>(p, dim3(8, 64, 1), sV);
        cudaEventRecord(evV[it], sV);

        clear(p);                                   /* qk only (N = 2*Dsz) */
        p.A = p_ln;   p.lda = Dsz;
        p.W = d_qkv_w; p.ldw = Dsz;
        p.bias = d_qkv_b;
        p.C = p_big;  p.ldc = 3 * Dsz;
        p.M = BS; p.N = 2 * Dsz; p.K = Dsz;
        p.sel = p_sel; p.selStep = step;
        p.selW = (ll)3 * Dsz * Dsz; p.selB = 3 * Dsz;
        launch_gemm<1, true>(p, dim3(16, 64, 1), s0);

        clear(p);                                   /* expscores + partial rowsums */
        p.A = p_big;          p.lda = 3 * Dsz; p.aO = (ll)Ssz * 3 * Dsz; p.aI = HDsz;
        p.W = p_big + Dsz;    p.ldw = 3 * Dsz; p.wO = (ll)Ssz * 3 * Dsz; p.wI = HDsz;
        p.C = p_sc;           p.ldc = Ssz;     p.cO = (ll)Hsz * Ssz * Ssz; p.cI = (ll)Ssz * Ssz;
        p.zdiv = Hsz;
        p.M = Ssz; p.N = Ssz; p.K = HDsz;
        p.alpha = 0.0625f;
        p.rsp = p_rsp;
        launch_gemm<7, true>(p, dim3(16, 16, Bsz * Hsz), s0);

        rowsum2_k<<<Bsz * Hsz * Ssz / 256, 256, 0, s0>>>(p_rsp, p_rs);

        cudaStreamWaitEvent(s0, evV[it], 0);        /* PV needs v */
        clear(p);                                   /* att = (P v) / rowsum */
        p.A = p_sc;             p.lda = Ssz;     p.aO = (ll)Hsz * Ssz * Ssz; p.aI = (ll)Ssz * Ssz;
        p.W = p_big + 2 * Dsz;  p.ldw = 3 * Dsz; p.wO = (ll)Ssz * 3 * Dsz;  p.wI = HDsz;
        p.C = p_att;            p.ldc = Dsz;     p.cO = (ll)Ssz * Dsz;      p.cI = HDsz;
        p.zdiv = Hsz;
        p.M = Ssz; p.N = HDsz; p.K = Ssz;
        p.tf = p_rs;
        launch_gemm<8, false>(p, dim3(2, 16, Bsz * Hsz), s0);

        clear(p);                                   /* out-proj residual */
        p.A = p_att;  p.lda = Dsz;
        p.W = d_out_w; p.ldw = Dsz;
        p.bias = d_out_b;
        p.C = p_dmid; p.ldc = Dsz;
        p.M = BS; p.N = Dsz; p.K = Dsz;
        p.X = xin; p.ldx = Dsz; p.tf = tf; p.delayed = p_md;
        p.sel = p_sel; p.selStep = step;
        p.selW = (ll)Dsz * Dsz; p.selB = Dsz;
        launch_gemm<5, true>(p, dim3(8, 64, 1), s0);

        ln_k<<<BS, 256, 0, s0>>>(p_dmid, p_ln, d_ln2_s, d_ln2_b, p_sel, step);

        clear(p);                                   /* ff1 + gelu */
        p.A = p_ln;    p.lda = Dsz;
        p.W = d_ff1_w; p.ldw = Dsz;
        p.bias = d_ff1_b;
        p.C = p_big;   p.ldc = 4 * Dsz;
        p.M = BS; p.N = 4 * Dsz; p.K = Dsz;
        p.sel = p_sel; p.selStep = step;
        p.selW = (ll)4 * Dsz * Dsz; p.selB = 4 * Dsz;
        launch_gemm<3, true>(p, dim3(32, 64, 1), s0);

        clear(p);                                   /* ff2 + residual */
        p.A = p_big;   p.lda = 4 * Dsz;
        p.W = d_ff2_w; p.ldw = 4 * Dsz;
        p.bias = d_ff2_b;
        p.C = xout;    p.ldc = Dsz;
        p.M = BS; p.N = Dsz; p.K = 4 * Dsz;
        p.X = p_dmid; p.ldx = Dsz;
        p.sel = p_sel; p.selStep = step;
        p.selW = (ll)Dsz * 4 * Dsz; p.selB = Dsz;
        launch_gemm<6, true>(p, dim3(8, 64, 1), s0);
    }

    cudaEventRecord(evJoin, sE);
    cudaStreamWaitEvent(s0, evJoin, 0);
}

// round 17
// speedup vs baseline: 1.0062x; 1.0062x over previous
#include <cuda_runtime.h>
#include <math.h>
#include <stdint.h>

#define Bsz 4
#define Ssz 2048
#define Dsz 1024
#define Hsz 4
#define HDsz 256
#define BS (Bsz*Ssz)          /* 8192 rows */
typedef long long ll;

/* ------------------------------------------------------------------ */
/* scratch (device globals — no allocation in kernel_launch)          */
/* ------------------------------------------------------------------ */
__device__ float g_ln  [(ll)BS*Dsz];
__device__ float g_lnE [(ll)BS*Dsz];
__device__ float g_big [(ll)BS*4*Dsz];
__device__ float g_mid [(ll)BS*Dsz];
__device__ float g_att [(ll)BS*Dsz];
__device__ float g_e1  [(ll)BS*Dsz];
__device__ float g_d1  [(ll)BS*Dsz];
__device__ float g_dmid[(ll)BS*Dsz];
__device__ float g_sc  [(ll)Bsz*Hsz*Ssz*Ssz];
__device__ float g_rsp [(ll)Bsz*Hsz*Ssz*16];
__device__ float g_rs  [(ll)Bsz*Hsz*Ssz];
__device__ float g_meanp[(ll)256*Dsz];
__device__ float g_mean_e[Bsz*Dsz];
__device__ float g_mean_d[Bsz*Dsz];
__device__ int   g_sel[4];

/* ------------------------------------------------------------------ */
__global__ void __launch_bounds__(256) mean1b_k(const float* __restrict__ x0,
                                                const float* __restrict__ x1,
                                                float* __restrict__ partial) {
    int blk = blockIdx.x;
    const float* x = (blk < 128) ? x0 : x1;
    int lb = blk & 127;
    int b = lb >> 5, ch = lb & 31;
    const float* p = x + (ll)b * Ssz * Dsz + (ll)ch * 64 * Dsz;
    int d4 = threadIdx.x;
    float4 acc = make_float4(0.f, 0.f, 0.f, 0.f);
    for (int r = 0; r < 64; r++) {
        float4 v = *(const float4*)(p + (ll)r * Dsz + d4 * 4);
        acc.x += v.x; acc.y += v.y; acc.z += v.z; acc.w += v.w;
    }
    *(float4*)(partial + (ll)blk * Dsz + d4 * 4) = acc;
}
__global__ void mean2b_k(const float* __restrict__ partial,
                         float* __restrict__ oe, float* __restrict__ od) {
    int idx = blockIdx.x * blockDim.x + threadIdx.x;
    if (idx >= 2 * Bsz * Dsz) return;
    int half = idx / (Bsz * Dsz);
    int li = idx - half * (Bsz * Dsz);
    int b = li / Dsz, d = li % Dsz;
    const float* p = partial + (ll)half * 128 * Dsz + (ll)b * 32 * Dsz + d;
    float s = 0.f;
    #pragma unroll
    for (int c = 0; c < 32; c++) s += p[(ll)c * Dsz];
    float* out = half ? od : oe;
    out[li] = s * (1.0f / Ssz);
}

__global__ void route2_k(const float* __restrict__ me, const float* __restrict__ md,
                         const float* __restrict__ esw, const float* __restrict__ esb,
                         const float* __restrict__ dsw, const float* __restrict__ dsb,
                         int* __restrict__ selOut) {
    int zz = blockIdx.x;
    const float* mean0 = zz ? md : me;
    const float* selw  = zz ? dsw : esw;
    const float* selb  = zz ? dsb : esb;
    int* out = selOut + zz * 2;
    __shared__ float sc[8];
    int w = threadIdx.x >> 5, lane = threadIdx.x & 31;
    float s = 0.f;
    for (int i = lane; i < Dsz; i += 32) s += mean0[i] * selw[w * Dsz + i];
    #pragma unroll
    for (int o = 16; o; o >>= 1) s += __shfl_down_sync(0xffffffff, s, o);
    if (lane == 0) sc[w] = s + selb[w];
    __syncthreads();
    if (threadIdx.x == 0) {
        int i0 = 0;
        for (int i = 1; i < 8; i++) if (sc[i] > sc[i0]) i0 = i;
        int i1 = -1;
        for (int i = 0; i < 8; i++)
            if (i != i0 && (i1 < 0 || sc[i] > sc[i1])) i1 = i;
        out[0] = i0; out[1] = i1;
    }
}

__global__ void __launch_bounds__(256) ln_k(const float* __restrict__ x,
                                            float* __restrict__ y,
                                            const float* __restrict__ sBase,
                                            const float* __restrict__ bBase,
                                            const int* __restrict__ sel, int step) {
    int row = blockIdx.x;
    const float* xr = x + (ll)row * Dsz;
    float*       yr = y + (ll)row * Dsz;
    int s = sel[step];
    const float* sc = sBase + (ll)s * Dsz;
    const float* bi = bBase + (ll)s * Dsz;
    int tid = threadIdx.x;
    float4 v = *(const float4*)(xr + tid * 4);
    float sum = v.x + v.y + v.z + v.w;
    float sq  = v.x*v.x + v.y*v.y + v.z*v.z + v.w*v.w;
    __shared__ float ssum[256], ssq[256];
    ssum[tid] = sum; ssq[tid] = sq;
    __syncthreads();
    for (int o = 128; o > 0; o >>= 1) {
        if (tid < o) { ssum[tid] += ssum[tid+o]; ssq[tid] += ssq[tid+o]; }
        __syncthreads();
    }
    float mean = ssum[0] * (1.0f / Dsz);
    float var  = ssq[0] * (1.0f / Dsz) - mean * mean;
    float inv  = rsqrtf(var + 1e-5f);
    float4 s4 = *(const float4*)(sc + tid * 4);
    float4 b4 = *(const float4*)(bi + tid * 4);
    float4 o4;
    o4.x = (v.x - mean) * inv * s4.x + b4.x;
    o4.y = (v.y - mean) * inv * s4.y + b4.y;
    o4.z = (v.z - mean) * inv * s4.z + b4.z;
    o4.w = (v.w - mean) * inv * s4.w + b4.w;
    *(float4*)(yr + tid * 4) = o4;
}

__global__ void rowsum2_k(const float* __restrict__ rsp, float* __restrict__ rs) {
    int row = blockIdx.x * 256 + threadIdx.x;
    const float* p = rsp + (ll)row * 16;
    float s = 0.f;
    #pragma unroll
    for (int i = 0; i < 16; i++) s += p[i];
    rs[row] = s;
}

/* ------------------------------------------------------------------ */
/* tf32 tensor-core GEMM, 128x128 tile, 3-stage cp.async, ldmatrix    */
/* EPI: 0 none 1 +bias 2 tanh 3 gelu 4 emb-res 5 outproj-res 6 ff2-res*/
/*      7 exp(alpha*g) + partial row sums   8 g/rowsum[z*2048+m]      */
/* ------------------------------------------------------------------ */
struct GemmP {
    const float* A; int lda; ll aO, aI;
    const float* W; int ldw; ll wO, wI;
    const float* bias;
    float* C; int ldc; ll cO, cI;
    int zdiv;
    int M, N, K;
    float alpha;
    const float* X; int ldx; ll xO, xI;
    const float* tf; const float* delayed;
    float* rsp;
    int Srows;
    const int* sel; int selStep; ll selW, selB;
};

__device__ __forceinline__ void mma_tf32(float4& c,
        uint32_t a0, uint32_t a1, uint32_t a2, uint32_t a3,
        uint32_t b0, uint32_t b1) {
    asm volatile(
        "mma.sync.aligned.m16n8k8.row.col.f32.tf32.tf32.f32 "
        "{%0,%1,%2,%3}, {%4,%5,%6,%7}, {%8,%9}, {%0,%1,%2,%3};"
        : "+f"(c.x), "+f"(c.y), "+f"(c.z), "+f"(c.w)
        : "r"(a0), "r"(a1), "r"(a2), "r"(a3), "r"(b0), "r"(b1));
}

__device__ __forceinline__ void cp_async16(void* dst, const void* src) {
    uint32_t s = (uint32_t)__cvta_generic_to_shared(dst);
    asm volatile("cp.async.cg.shared.global [%0], [%1], 16;" :: "r"(s), "l"(src));
}

__device__ __forceinline__ void ldm_x4(uint32_t* r, uint32_t addr) {
    asm volatile("ldmatrix.sync.aligned.m8n8.x4.shared.b16 {%0,%1,%2,%3}, [%4];"
        : "=r"(r[0]), "=r"(r[1]), "=r"(r[2]), "=r"(r[3]) : "r"(addr));
}

#define APAD 20     /* 16 + 4 pad, K-major row stride  */
#define BPAD 136    /* 128 + 8 pad, N-major row stride */
#define A_ELEMS (128*APAD)
#define BT_ELEMS (128*APAD)
#define BF_ELEMS (16*BPAD)

template<int EPI, bool BT>
__global__ void __launch_bounds__(256) gemm_k(GemmP p) {
    extern __shared__ float smem[];
    const int B_ELEMS = BT ? BT_ELEMS : BF_ELEMS;
    float* AsBase = smem;
    float* BsBase = smem + 3 * A_ELEMS;

    int z = blockIdx.z;
    int zo = z / p.zdiv, zi = z % p.zdiv;
    const float* A = p.A + zo * p.aO + zi * p.aI;
    const float* W = p.W + zo * p.wO + zi * p.wI;
    float*       C = p.C + zo * p.cO + zi * p.cI;
    const float* X = p.X ? (p.X + zo * p.xO + zi * p.xI) : nullptr;
    const float* bias = p.bias;
    if (p.sel) {
        int s = p.sel[p.selStep];
        W += (ll)s * p.selW;
        if (bias) bias += (ll)s * p.selB;
    }
    int m0 = blockIdx.y * 128, n0 = blockIdx.x * 128;
    int tid  = threadIdx.x;
    int lane = tid & 31;
    int warp = tid >> 5;
    int warpM = warp >> 2;
    int warpN = warp & 3;
    int lr = lane >> 2;
    int lc = lane & 3;

    int aRowSel = lane & 15;
    int aColSel = (lane >> 4) * 4;
    int bRowSel = (lane & 7) + ((lane >> 4) << 3);
    int bColSel = ((lane >> 3) & 1) * 4;

    uint32_t aBaseU = (uint32_t)__cvta_generic_to_shared(AsBase);
    uint32_t bBaseU = (uint32_t)__cvta_generic_to_shared(BsBase);

    float4 acc[4][4];
    #pragma unroll
    for (int i = 0; i < 4; i++)
        #pragma unroll
        for (int j = 0; j < 4; j++) acc[i][j] = make_float4(0.f, 0.f, 0.f, 0.f);

    auto issueStage = [&](int stage, int k0) {
        float* Ad = AsBase + stage * A_ELEMS;
        #pragma unroll
        for (int l = 0; l < 2; l++) {
            int idx = tid + l * 256;
            int r = idx >> 2, c4 = idx & 3;
            cp_async16(Ad + r * APAD + c4 * 4,
                       A + (ll)(m0 + r) * p.lda + k0 + c4 * 4);
        }
        float* Bd = BsBase + stage * B_ELEMS;
        if (BT) {
            #pragma unroll
            for (int l = 0; l < 2; l++) {
                int idx = tid + l * 256;
                int r = idx >> 2, c4 = idx & 3;
                cp_async16(Bd + r * APAD + c4 * 4,
                           W + (ll)(n0 + r) * p.ldw + k0 + c4 * 4);
            }
        } else {
            #pragma unroll
            for (int l = 0; l < 2; l++) {
                int idx = tid + l * 256;
                int kr = idx >> 5, c4 = idx & 31;
                cp_async16(Bd + kr * BPAD + c4 * 4,
                           W + (ll)(k0 + kr) * p.ldw + n0 + c4 * 4);
            }
        }
        asm volatile("cp.async.commit_group;" ::: "memory");
    };

    int nStages = p.K >> 4;
    issueStage(0, 0);
    if (nStages > 1) issueStage(1, 16);

    int s = 0;
    for (int i = 0; i < nStages; i++) {
        asm volatile("cp.async.wait_group 1;" ::: "memory");
        __syncthreads();
        if (i + 2 < nStages) {
            int ns = s + 2; if (ns >= 3) ns -= 3;
            issueStage(ns, (i + 2) << 4);
        }

        uint32_t aS = aBaseU + (s * A_ELEMS) * 4;
        uint32_t bS = bBaseU + (s * B_ELEMS) * 4;
        const float* Bsb = BsBase + s * B_ELEMS;

        #pragma unroll
        for (int kc = 0; kc < 2; kc++) {
            int kb = kc * 8;
            uint32_t af[4][4];
            #pragma unroll
            for (int mf = 0; mf < 4; mf++) {
                int rb = warpM * 64 + mf * 16;
                uint32_t addr = aS + (uint32_t)(((rb + aRowSel) * APAD + kb + aColSel) * 4);
                ldm_x4(af[mf], addr);
            }
            uint32_t bf[2][4];
            if (BT) {
                #pragma unroll
                for (int pr = 0; pr < 2; pr++) {
                    int nb = warpN * 32 + pr * 16;
                    uint32_t addr = bS + (uint32_t)(((nb + bRowSel) * APAD + kb + bColSel) * 4);
                    ldm_x4(bf[pr], addr);
                }
            } else {
                #pragma unroll
                for (int nf = 0; nf < 4; nf++) {
                    int nb = warpN * 32 + nf * 8;
                    bf[nf >> 1][(nf & 1) * 2    ] = __float_as_uint(Bsb[(kb + lc    ) * BPAD + nb + lr]);
                    bf[nf >> 1][(nf & 1) * 2 + 1] = __float_as_uint(Bsb[(kb + lc + 4) * BPAD + nb + lr]);
                }
            }
            #pragma unroll
            for (int mf = 0; mf < 4; mf++)
                #pragma unroll
                for (int nf = 0; nf < 4; nf++)
                    mma_tf32(acc[mf][nf],
                             af[mf][0], af[mf][1], af[mf][2], af[mf][3],
                             bf[nf >> 1][(nf & 1) * 2], bf[nf >> 1][(nf & 1) * 2 + 1]);
        }
        s++; if (s >= 3) s = 0;
    }

    /* epilogue */
    float rowPart[4][2];
    #pragma unroll
    for (int i = 0; i < 4; i++) { rowPart[i][0] = 0.f; rowPart[i][1] = 0.f; }

    #pragma unroll
    for (int mf = 0; mf < 4; mf++) {
        #pragma unroll
        for (int nf = 0; nf < 4; nf++) {
            float4 c = acc[mf][nf];
            float vals[4] = {c.x, c.y, c.z, c.w};
            #pragma unroll
            for (int e = 0; e < 4; e++) {
                int m = m0 + warpM * 64 + mf * 16 + lr + (e >= 2 ? 8 : 0);
                int n = n0 + warpN * 32 + nf * 8 + lc * 2 + (e & 1);
                int bb = m / p.Srows;
                float g = vals[e] * p.alpha;
                if (EPI >= 1 && EPI <= 6) g += bias[n];
                float r;
                if      (EPI == 0) r = g;
                else if (EPI == 1) r = g;
                else if (EPI == 2) r = tanhf(g);
                else if (EPI == 3) r = 0.5f * g * (1.0f + erff(g * 0.7071067811865475f));
                else if (EPI == 4) r = X[(ll)m * p.ldx + n]
                                       + g * (1.0f + p.tf[bb * Dsz + n] * 0.1f) * 0.3f;
                else if (EPI == 5) r = X[(ll)m * p.ldx + n]
                                       + (g + p.delayed[bb * Dsz + n] * 0.3f)
                                         * (1.0f + p.tf[bb * Dsz + n] * 0.05f) * 0.5f;
                else if (EPI == 6) r = X[(ll)m * p.ldx + n] + g * 0.5f;
                else if (EPI == 7) { r = __expf(g); rowPart[mf][e >> 1] += r; }
                else               r = g / p.tf[(ll)z * Ssz + m];   /* EPI 8 */
                C[(ll)m * p.ldc + n] = r;
            }
        }
    }

    if (EPI == 7) {
        __syncthreads();
        float* sPart = smem;
        #pragma unroll
        for (int mf = 0; mf < 4; mf++)
            #pragma unroll
            for (int e2 = 0; e2 < 2; e2++) {
                float v = rowPart[mf][e2];
                v += __shfl_xor_sync(0xffffffff, v, 1);
                v += __shfl_xor_sync(0xffffffff, v, 2);
                if (lc == 0) {
                    int rl = warpM * 64 + mf * 16 + lr + e2 * 8;
                    sPart[rl * 4 + warpN] = v;
                }
            }
        __syncthreads();
        if (tid < 128) {
            float t = sPart[tid * 4 + 0] + sPart[tid * 4 + 1]
                    + sPart[tid * 4 + 2] + sPart[tid * 4 + 3];
            p.rsp[((ll)z * Ssz + m0 + tid) * 16 + blockIdx.x] = t;
        }
    }
}

/* ------------------------------------------------------------------ */
#define SMEM_BT ((3*A_ELEMS + 3*BT_ELEMS) * (int)sizeof(float))
#define SMEM_BF ((3*A_ELEMS + 3*BF_ELEMS) * (int)sizeof(float))

template<int EPI, bool BT>
static void launch_gemm(const GemmP& p, dim3 grid, cudaStream_t st) {
    static bool done = false;
    if (!done) {
        cudaFuncSetAttribute(gemm_k<EPI, BT>,
                             cudaFuncAttributeMaxDynamicSharedMemorySize,
                             BT ? SMEM_BT : SMEM_BF);
        done = true;
    }
    gemm_k<EPI, BT><<<grid, 256, BT ? SMEM_BT : SMEM_BF, st>>>(p);
}

extern "C" void kernel_launch(void* const* d_in, const int* in_sizes, int n_in,
                              void* d_out, int out_size) {
    const float* emb_in  = (const float*)d_in[0];
    const float* dis_in  = (const float*)d_in[1];
    const float* tf      = (const float*)d_in[2];
    const float* esel_w  = (const float*)d_in[3];
    const float* esel_b  = (const float*)d_in[4];
    const float* e_ln_s  = (const float*)d_in[5];
    const float* e_ln_b  = (const float*)d_in[6];
    const float* e_w1    = (const float*)d_in[7];
    const float* e_b1    = (const float*)d_in[8];
    const float* e_w2    = (const float*)d_in[9];
    const float* e_b2    = (const float*)d_in[10];
    const float* dsel_w  = (const float*)d_in[11];
    const float* dsel_b  = (const float*)d_in[12];
    const float* d_ln1_s = (const float*)d_in[13];
    const float* d_ln1_b = (const float*)d_in[14];
    const float* d_qkv_w = (const float*)d_in[15];
    const float* d_qkv_b = (const float*)d_in[16];
    const float* d_out_w = (const float*)d_in[17];
    const float* d_out_b = (const float*)d_in[18];
    const float* d_ln2_s = (const float*)d_in[19];
    const float* d_ln2_b = (const float*)d_in[20];
    const float* d_ff1_w = (const float*)d_in[21];
    const float* d_ff1_b = (const float*)d_in[22];
    const float* d_ff2_w = (const float*)d_in[23];
    const float* d_ff2_b = (const float*)d_in[24];

    float *p_ln, *p_lnE, *p_big, *p_mid, *p_att, *p_e1, *p_d1, *p_dmid, *p_sc,
          *p_rsp, *p_rs, *p_mp, *p_me, *p_md;
    int   *p_sel;
    cudaGetSymbolAddress((void**)&p_ln,   g_ln);
    cudaGetSymbolAddress((void**)&p_lnE,  g_lnE);
    cudaGetSymbolAddress((void**)&p_big,  g_big);
    cudaGetSymbolAddress((void**)&p_mid,  g_mid);
    cudaGetSymbolAddress((void**)&p_att,  g_att);
    cudaGetSymbolAddress((void**)&p_e1,   g_e1);
    cudaGetSymbolAddress((void**)&p_d1,   g_d1);
    cudaGetSymbolAddress((void**)&p_dmid, g_dmid);
    cudaGetSymbolAddress((void**)&p_sc,   g_sc);
    cudaGetSymbolAddress((void**)&p_rsp,  g_rsp);
    cudaGetSymbolAddress((void**)&p_rs,   g_rs);
    cudaGetSymbolAddress((void**)&p_mp,   g_meanp);
    cudaGetSymbolAddress((void**)&p_me,   g_mean_e);
    cudaGetSymbolAddress((void**)&p_md,   g_mean_d);
    cudaGetSymbolAddress((void**)&p_sel,  g_sel);

    float* out_h  = (float*)d_out;
    float* out_dh = (float*)d_out + (ll)BS * Dsz;

    /* one-time stream/event setup; sE gets LOWEST priority so the
       embodied path fills scheduling gaps instead of competing with the
       disembodied critical path */
    static cudaStream_t sE = nullptr;
    static cudaEvent_t evFork = nullptr, evJoin = nullptr;
    if (!sE) {
        int prLeast, prGreatest;
        cudaDeviceGetStreamPriorityRange(&prLeast, &prGreatest);
        cudaStreamCreateWithPriority(&sE, cudaStreamNonBlocking, prLeast);
        cudaEventCreateWithFlags(&evFork, cudaEventDisableTiming);
        cudaEventCreateWithFlags(&evJoin, cudaEventDisableTiming);
    }
    cudaStream_t s0 = 0;

    /* means + routing (batched prologue on main stream) */
    mean1b_k<<<256, 256, 0, s0>>>(emb_in, dis_in, p_mp);
    mean2b_k<<<32, 256, 0, s0>>>(p_mp, p_me, p_md);
    route2_k<<<2, 256, 0, s0>>>(p_me, p_md, esel_w, esel_b, dsel_w, dsel_b, p_sel);

    /* fork: embodied path runs on low-priority sE */
    cudaEventRecord(evFork, s0);
    cudaStreamWaitEvent(sE, evFork, 0);

    GemmP p;
    auto clear = [&](GemmP& q) {
        q.aO=q.aI=q.wO=q.wI=q.cO=q.cI=q.xO=q.xI=0; q.zdiv=1;
        q.alpha=1.0f; q.X=nullptr; q.ldx=0; q.tf=nullptr; q.delayed=nullptr;
        q.rsp=nullptr;
        q.Srows=Ssz; q.sel=nullptr; q.selStep=0; q.selW=0; q.selB=0; q.bias=nullptr;
    };

    /* ---------------- embodied path (stream sE, low priority) ------- */
    for (int it = 0; it < 2; it++) {
        const float* xin  = (it == 0) ? emb_in : p_e1;
        float*       xout = (it == 0) ? p_e1   : out_h;

        ln_k<<<BS, 256, 0, sE>>>(xin, p_lnE, e_ln_s, e_ln_b, p_sel, it);

        clear(p);
        p.A = p_lnE; p.lda = Dsz;
        p.W = e_w1;  p.ldw = Dsz;
        p.bias = e_b1;
        p.C = p_mid; p.ldc = Dsz;
        p.M = BS; p.N = Dsz; p.K = Dsz;
        p.sel = p_sel; p.selStep = it;
        p.selW = (ll)Dsz * Dsz; p.selB = Dsz;
        launch_gemm<2, true>(p, dim3(8, 64, 1), sE);

        clear(p);
        p.A = p_mid; p.lda = Dsz;
        p.W = e_w2;  p.ldw = Dsz;
        p.bias = e_b2;
        p.C = xout;  p.ldc = Dsz;
        p.M = BS; p.N = Dsz; p.K = Dsz;
        p.X = xin; p.ldx = Dsz; p.tf = tf;
        p.sel = p_sel; p.selStep = it;
        p.selW = (ll)Dsz * Dsz; p.selB = Dsz;
        launch_gemm<4, true>(p, dim3(8, 64, 1), sE);
    }

    /* ---------------- disembodied path (stream s0) ---------------- */
    for (int it = 0; it < 2; it++) {
        const float* xin  = (it == 0) ? dis_in : p_d1;
        float*       xout = (it == 0) ? p_d1   : out_dh;
        int step = 2 + it;

        ln_k<<<BS, 256, 0, s0>>>(xin, p_ln, d_ln1_s, d_ln1_b, p_sel, step);

        clear(p);                                   /* qkv */
        p.A = p_ln;   p.lda = Dsz;
        p.W = d_qkv_w; p.ldw = Dsz;
        p.bias = d_qkv_b;
        p.C = p_big;  p.ldc = 3 * Dsz;
        p.M = BS; p.N = 3 * Dsz; p.K = Dsz;
        p.sel = p_sel; p.selStep = step;
        p.selW = (ll)3 * Dsz * Dsz; p.selB = 3 * Dsz;
        launch_gemm<1, true>(p, dim3(24, 64, 1), s0);

        clear(p);                                   /* expscores + partial rowsums */
        p.A = p_big;          p.lda = 3 * Dsz; p.aO = (ll)Ssz * 3 * Dsz; p.aI = HDsz;
        p.W = p_big + Dsz;    p.ldw = 3 * Dsz; p.wO = (ll)Ssz * 3 * Dsz; p.wI = HDsz;
        p.C = p_sc;           p.ldc = Ssz;     p.cO = (ll)Hsz * Ssz * Ssz; p.cI = (ll)Ssz * Ssz;
        p.zdiv = Hsz;
        p.M = Ssz; p.N = Ssz; p.K = HDsz;
        p.alpha = 0.0625f;
        p.rsp = p_rsp;
        launch_gemm<7, true>(p, dim3(16, 16, Bsz * Hsz), s0);

        rowsum2_k<<<Bsz * Hsz * Ssz / 256, 256, 0, s0>>>(p_rsp, p_rs);

        clear(p);                                   /* att = (P v) / rowsum */
        p.A = p_sc;             p.lda = Ssz;     p.aO = (ll)Hsz * Ssz * Ssz; p.aI = (ll)Ssz * Ssz;
        p.W = p_big + 2 * Dsz;  p.ldw = 3 * Dsz; p.wO = (ll)Ssz * 3 * Dsz;  p.wI = HDsz;
        p.C = p_att;            p.ldc = Dsz;     p.cO = (ll)Ssz * Dsz;      p.cI = HDsz;
        p.zdiv = Hsz;
        p.M = Ssz; p.N = HDsz; p.K = Ssz;
        p.tf = p_rs;
        launch_gemm<8, false>(p, dim3(2, 16, Bsz * Hsz), s0);

        clear(p);                                   /* out-proj residual */
        p.A = p_att;  p.lda = Dsz;
        p.W = d_out_w; p.ldw = Dsz;
        p.bias = d_out_b;
        p.C = p_dmid; p.ldc = Dsz;
        p.M = BS; p.N = Dsz; p.K = Dsz;
        p.X = xin; p.ldx = Dsz; p.tf = tf; p.delayed = p_md;
        p.sel = p_sel; p.selStep = step;
        p.selW = (ll)Dsz * Dsz; p.selB = Dsz;
        launch_gemm<5, true>(p, dim3(8, 64, 1), s0);

        ln_k<<<BS, 256, 0, s0>>>(p_dmid, p_ln, d_ln2_s, d_ln2_b, p_sel, step);

        clear(p);                                   /* ff1 + gelu */
        p.A = p_ln;    p.lda = Dsz;
        p.W = d_ff1_w; p.ldw = Dsz;
        p.bias = d_ff1_b;
        p.C = p_big;   p.ldc = 4 * Dsz;
        p.M = BS; p.N = 4 * Dsz; p.K = Dsz;
        p.sel = p_sel; p.selStep = step;
        p.selW = (ll)4 * Dsz * Dsz; p.selB = 4 * Dsz;
        launch_gemm<3, true>(p, dim3(32, 64, 1), s0);

        clear(p);                                   /* ff2 + residual */
        p.A = p_big;   p.lda = 4 * Dsz;
        p.W = d_ff2_w; p.ldw = 4 * Dsz;
        p.bias = d_ff2_b;
        p.C = xout;    p.ldc = Dsz;
        p.M = BS; p.N = Dsz; p.K = 4 * Dsz;
        p.X = p_dmid; p.ldx = Dsz;
        p.sel = p_sel; p.selStep = step;
        p.selW = (ll)Dsz * 4 * Dsz; p.selB = Dsz;
        launch_gemm<6, true>(p, dim3(8, 64, 1), s0);
    }

    /* join: main stream waits for the embodied path before returning */
    cudaEventRecord(evJoin, sE);
    cudaStreamWaitEvent(s0, evJoin, 0);
}